// round 4
// baseline (speedup 1.0000x reference)
#include <cuda_runtime.h>
#include <cuda_bf16.h>
#include <math.h>

#define NB   16
#define CI   128
#define HH   40
#define WW   200
#define PP   (HH*WW)
#define KK   64

// ------------------------- scratch (static device) -------------------------
__device__ float d_a     [NB*KK*PP];            // soft assignment [n][k][p]
__device__ float d_asum  [NB*KK];
__device__ float d_vladp [8*NB*KK*CI];          // split-K partials [s][n][k][c]
__device__ float d_pool1 [NB*256*20*100];
__device__ float d_h2    [NB*512*20*100];
__device__ float d_pool2 [NB*512*5*25];
__device__ float d_xf    [NB*1024];
__device__ float d_feat  [NB*9216];

// ---------------------------------------------------------------------------
// 1) soft-assignment: 1x1-conv logits + softmax over K.  grid(50,16), 256 thr
// ---------------------------------------------------------------------------
__global__ void __launch_bounds__(256) assign_kernel(
    const float* __restrict__ x, const float* __restrict__ cw,
    const float* __restrict__ cb)
{
    extern __shared__ float smem[];
    float* sX = smem;             // [128][160]
    float* sW = sX + 128*160;     // [64][128]
    float* sB = sW + 64*128;      // [64]
    float* sL = sB + 64;          // [64][160]

    int tid = threadIdx.x;
    int n   = blockIdx.y;
    int p0  = blockIdx.x * 160;

    for (int idx = tid; idx < 128*160; idx += 256) {
        int c = idx / 160, pp = idx - c*160;
        sX[idx] = x[((long)n*CI + c)*PP + p0 + pp];
    }
    for (int idx = tid; idx < 64*128; idx += 256) sW[idx] = cw[idx];
    if (tid < 64) sB[tid] = cb[tid];
    __syncthreads();

    // phase A: logits GEMM. thread = (kg 0..7) x (pg 0..31): 8k x 5p
    int pg = tid & 31, kg = tid >> 5;
    float acc[8][5];
    #pragma unroll
    for (int o = 0; o < 8; o++) {
        float b = sB[kg*8 + o];
        #pragma unroll
        for (int j = 0; j < 5; j++) acc[o][j] = b;
    }
    for (int c = 0; c < 128; c++) {
        float xv[5];
        #pragma unroll
        for (int j = 0; j < 5; j++) xv[j] = sX[c*160 + pg*5 + j];
        #pragma unroll
        for (int o = 0; o < 8; o++) {
            float wv = sW[(kg*8 + o)*128 + c];
            #pragma unroll
            for (int j = 0; j < 5; j++) acc[o][j] += wv * xv[j];
        }
    }
    #pragma unroll
    for (int o = 0; o < 8; o++)
        #pragma unroll
        for (int j = 0; j < 5; j++)
            sL[(kg*8 + o)*160 + pg*5 + j] = acc[o][j];
    __syncthreads();

    // phase B: softmax over K per pixel
    if (tid < 160) {
        int p = tid;
        float mx = -3.4e38f;
        #pragma unroll
        for (int k = 0; k < 64; k++) mx = fmaxf(mx, sL[k*160 + p]);
        float e[64];
        float s = 0.f;
        #pragma unroll
        for (int k = 0; k < 64; k++) { e[k] = expf(sL[k*160 + p] - mx); s += e[k]; }
        float inv = 1.f / s;
        float* ap = d_a + ((long)n*KK)*PP + p0 + p;
        #pragma unroll
        for (int k = 0; k < 64; k++) ap[(long)k*PP] = e[k]*inv;
    }
}

// ---------------------------------------------------------------------------
// 2) asum[n,k] = sum_p a[n,k,p].   grid 1024, 256 thr
// ---------------------------------------------------------------------------
__global__ void asum_kernel()
{
    __shared__ float sred[256];
    int row = blockIdx.x;
    const float* ap = d_a + (long)row*PP;
    float s = 0.f;
    for (int i = threadIdx.x; i < PP; i += 256) s += ap[i];
    sred[threadIdx.x] = s; __syncthreads();
    for (int st = 128; st > 0; st >>= 1) {
        if (threadIdx.x < st) sred[threadIdx.x] += sred[threadIdx.x + st];
        __syncthreads();
    }
    if (threadIdx.x == 0) d_asum[row] = sred[0];
}

// ---------------------------------------------------------------------------
// 3) VLAD GEMM partials over pixel splits.   grid(8,16), 256 thr
// ---------------------------------------------------------------------------
__global__ void __launch_bounds__(256) vlad_kernel(const float* __restrict__ x)
{
    __shared__ float sA [64*51];
    __shared__ float sX2[128*51];
    int tid = threadIdx.x;
    int split = blockIdx.x, n = blockIdx.y;
    int cg = tid & 31, kg = tid >> 5;
    float acc[8][4];
    #pragma unroll
    for (int o = 0; o < 8; o++)
        #pragma unroll
        for (int j = 0; j < 4; j++) acc[o][j] = 0.f;

    for (int ch = 0; ch < 20; ch++) {
        int pbase = split*1000 + ch*50;
        __syncthreads();
        for (int idx = tid; idx < 64*50; idx += 256) {
            int k = idx / 50, pp = idx - k*50;
            sA[k*51 + pp] = d_a[((long)n*KK + k)*PP + pbase + pp];
        }
        for (int idx = tid; idx < 128*50; idx += 256) {
            int c = idx / 50, pp = idx - c*50;
            sX2[c*51 + pp] = x[((long)n*CI + c)*PP + pbase + pp];
        }
        __syncthreads();
        for (int pp = 0; pp < 50; pp++) {
            float av[8];
            #pragma unroll
            for (int o = 0; o < 8; o++) av[o] = sA[(kg*8 + o)*51 + pp];
            #pragma unroll
            for (int j = 0; j < 4; j++) {
                float xv = sX2[(cg + 32*j)*51 + pp];
                #pragma unroll
                for (int o = 0; o < 8; o++) acc[o][j] += av[o]*xv;
            }
        }
    }
    #pragma unroll
    for (int o = 0; o < 8; o++)
        #pragma unroll
        for (int j = 0; j < 4; j++)
            d_vladp[(((long)split*NB + n)*KK + kg*8 + o)*CI + cg + 32*j] = acc[o][j];
}

// ---------------------------------------------------------------------------
// 4) VLAD reduce + center subtraction + intra L2 norm -> feat[:, :8192]
// ---------------------------------------------------------------------------
__global__ void vladreduce_kernel(const float* __restrict__ centers)
{
    __shared__ float sred[128];
    int row = blockIdx.x;                       // n*64+k
    int n = row >> 6, k = row & 63;
    int c = threadIdx.x;
    float v = -d_asum[row]*centers[k*CI + c];
    #pragma unroll
    for (int s = 0; s < 8; s++)
        v += d_vladp[(((long)s*NB + n)*KK + k)*CI + c];
    sred[c] = v*v; __syncthreads();
    for (int st = 64; st > 0; st >>= 1) {
        if (c < st) sred[c] += sred[c + st];
        __syncthreads();
    }
    float nrm = sqrtf(sred[0]);
    d_feat[(long)n*9216 + k*CI + c] = v / fmaxf(nrm, 1e-12f);
}

// ---------------------------------------------------------------------------
// 4b) global L2 over the 8192-dim VLAD block (reference's second l2norm)
// ---------------------------------------------------------------------------
__global__ void __launch_bounds__(256) vladglobal_kernel()
{
    __shared__ float sr[256];
    int n = blockIdx.x, tid = threadIdx.x;
    float* f = d_feat + (long)n*9216;
    float s = 0.f;
    for (int i = tid; i < 8192; i += 256) { float v = f[i]; s += v*v; }
    sr[tid] = s; __syncthreads();
    for (int st = 128; st > 0; st >>= 1) {
        if (tid < st) sr[tid] += sr[tid + st];
        __syncthreads();
    }
    float inv = 1.f / fmaxf(sqrtf(sr[0]), 1e-12f);
    for (int i = tid; i < 8192; i += 256) f[i] *= inv;
}

// ---------------------------------------------------------------------------
// 5) conv 5x5, pad 2. 2x2-pixel quad x 8 oc per thread, 160 thr.
//    tile = 4x20 output pixels, 64 oc per block, ic chunked by 8.
//    FUSEPOOL2: +LeakyReLU +2x2 maxpool -> d_pool1 ; else +LeakyReLU -> d_h2
// ---------------------------------------------------------------------------
template<int CIN, int HI, int WI, int COUT, bool FUSEPOOL2>
__global__ void __launch_bounds__(160, 3) conv5x5_kernel(
    const float* __restrict__ xin, const float* __restrict__ wgt,
    const float* __restrict__ bias)
{
    constexpr int ICB   = 8;
    constexpr int TILESX = WI / 20;
    constexpr int WROW  = ICB*25 + 1;
    extern __shared__ float smem[];
    float* sIn = smem;                  // [ICB][8][24]
    float* sW  = smem + ICB*8*24;       // [64][WROW]

    int tid = threadIdx.x;
    int q = tid % 20, og = tid / 20;
    int qy = q / 10, qx = q % 10;
    int tx = blockIdx.x % TILESX, ty = blockIdx.x / TILESX;
    int oy0 = ty*4, ox0 = tx*20;
    int n = blockIdx.z, ocb = blockIdx.y;
    const float* inN = (CIN == 128) ? (xin + (long)n*CIN*HI*WI)
                                    : (d_pool1 + (long)n*CIN*HI*WI);

    float acc[8][4];
    #pragma unroll
    for (int o = 0; o < 8; o++)
        #pragma unroll
        for (int j = 0; j < 4; j++) acc[o][j] = 0.f;

    #pragma unroll 1
    for (int ic0 = 0; ic0 < CIN; ic0 += ICB) {
        __syncthreads();
        for (int idx = tid; idx < ICB*8*24; idx += 160) {
            int ic = idx / (8*24); int rem = idx - ic*(8*24);
            int r = rem / 24, cc = rem - r*24;
            int iy = oy0 - 2 + r, ix = ox0 - 2 + cc;
            float v = 0.f;
            if (iy >= 0 && iy < HI && ix >= 0 && ix < WI)
                v = inN[((long)(ic0 + ic))*HI*WI + iy*WI + ix];
            sIn[idx] = v;
        }
        const float* wB = wgt + ((long)ocb*64)*CIN*25 + (long)ic0*25;
        for (int idx = tid; idx < 64*ICB*25; idx += 160) {
            int o = idx / (ICB*25); int t = idx - o*(ICB*25);
            sW[o*WROW + t] = wB[(long)o*CIN*25 + t];
        }
        __syncthreads();

        #pragma unroll 1
        for (int ic = 0; ic < ICB; ic++) {
            float xr[36];
            #pragma unroll
            for (int i = 0; i < 6; i++)
                #pragma unroll
                for (int j = 0; j < 6; j++)
                    xr[i*6 + j] = sIn[(ic*8 + 2*qy + i)*24 + 2*qx + j];
            const float* wRow = sW + og*8*WROW + ic*25;
            #pragma unroll
            for (int r = 0; r < 5; r++)
                #pragma unroll
                for (int s = 0; s < 5; s++) {
                    #pragma unroll
                    for (int o = 0; o < 8; o++) {
                        float wv = wRow[o*WROW + r*5 + s];
                        acc[o][0] += wv * xr[ r   *6 + s    ];
                        acc[o][1] += wv * xr[ r   *6 + s + 1];
                        acc[o][2] += wv * xr[(r+1)*6 + s    ];
                        acc[o][3] += wv * xr[(r+1)*6 + s + 1];
                    }
                }
        }
    }

    int ocBase = ocb*64 + og*8;
    if (FUSEPOOL2) {
        int py = ty*2 + qy, px = tx*10 + qx;
        #pragma unroll
        for (int o = 0; o < 8; o++) {
            float b = bias[ocBase + o];
            float m = -3.4e38f;
            #pragma unroll
            for (int j = 0; j < 4; j++) {
                float v = acc[o][j] + b;
                v = (v >= 0.f) ? v : 0.2f*v;
                m = fmaxf(m, v);
            }
            d_pool1[(((long)n*COUT + ocBase + o)*(HI/2) + py)*(WI/2) + px] = m;
        }
    } else {
        #pragma unroll
        for (int o = 0; o < 8; o++) {
            float b = bias[ocBase + o];
            #pragma unroll
            for (int j = 0; j < 4; j++) {
                int oy = oy0 + 2*qy + (j >> 1);
                int ox = ox0 + 2*qx + (j & 1);
                float v = acc[o][j] + b;
                v = (v >= 0.f) ? v : 0.2f*v;
                d_h2[(((long)n*COUT + ocBase + o)*HI + oy)*WI + ox] = v;
            }
        }
    }
}

// ---------------------------------------------------------------------------
// 6) 4x4 maxpool: d_h2[16,512,20,100] -> d_pool2[16,512,5,25]
// ---------------------------------------------------------------------------
__global__ void pool4_kernel()
{
    int idx = blockIdx.x*256 + threadIdx.x;       // 1,024,000
    int pw = idx % 25; int t = idx / 25;
    int ph = t % 5;  t /= 5;
    int ch = t % 512; int n = t / 512;
    const float* base = d_h2 + (((long)n*512 + ch)*20 + ph*4)*100 + pw*4;
    float m = -3.4e38f;
    #pragma unroll
    for (int i = 0; i < 4; i++)
        #pragma unroll
        for (int j = 0; j < 4; j++)
            m = fmaxf(m, base[i*100 + j]);
    d_pool2[idx] = m;
}

// ---------------------------------------------------------------------------
// 7) conv3 512->1024 5x5 pad2 on 5x25 + fused global maxpool -> d_xf
//    grid(ocb 0..15, n 0..15), 200 thr: ow(25) x og(8); 5 oh x 8 oc each
// ---------------------------------------------------------------------------
__global__ void __launch_bounds__(200) conv3_kernel(
    const float* __restrict__ w3, const float* __restrict__ b3)
{
    constexpr int ICB = 8;
    constexpr int WROW = ICB*25 + 1;
    extern __shared__ float smem[];
    float* sIn  = smem;                 // [8][9][29]
    float* sW   = sIn + ICB*9*29;       // [64][201]
    float* sred = sW + 64*WROW;         // [64][25]

    int tid = threadIdx.x;
    int ow = tid % 25, og = tid / 25;
    int ocb = blockIdx.x, n = blockIdx.y;

    float acc[8][5];
    #pragma unroll
    for (int o = 0; o < 8; o++)
        #pragma unroll
        for (int h = 0; h < 5; h++) acc[o][h] = 0.f;

    #pragma unroll 1
    for (int ic0 = 0; ic0 < 512; ic0 += ICB) {
        __syncthreads();
        for (int idx = tid; idx < ICB*9*29; idx += 200) {
            int ic = idx / (9*29); int rem = idx - ic*(9*29);
            int i = rem / 29, cc = rem - i*29;
            int iy = i - 2, ix = cc - 2;
            float v = 0.f;
            if (iy >= 0 && iy < 5 && ix >= 0 && ix < 25)
                v = d_pool2[(((long)n*512 + ic0 + ic)*5 + iy)*25 + ix];
            sIn[idx] = v;
        }
        const float* wB = w3 + ((long)ocb*64)*512*25 + (long)ic0*25;
        for (int idx = tid; idx < 64*ICB*25; idx += 200) {
            int o = idx / (ICB*25); int t = idx - o*(ICB*25);
            sW[o*WROW + t] = wB[(long)o*512*25 + t];
        }
        __syncthreads();

        #pragma unroll 1
        for (int ic = 0; ic < ICB; ic++) {
            float xr[45];                 // [9][5] column patch
            #pragma unroll
            for (int i = 0; i < 9; i++)
                #pragma unroll
                for (int j = 0; j < 5; j++)
                    xr[i*5 + j] = sIn[(ic*9 + i)*29 + ow + j];
            const float* wRow = sW + og*8*WROW + ic*25;
            #pragma unroll
            for (int r = 0; r < 5; r++)
                #pragma unroll
                for (int s = 0; s < 5; s++) {
                    #pragma unroll
                    for (int o = 0; o < 8; o++) {
                        float wv = wRow[o*WROW + r*5 + s];
                        #pragma unroll
                        for (int h = 0; h < 5; h++)
                            acc[o][h] += wv * xr[(h + r)*5 + s];
                    }
                }
        }
    }

    // bias + max over this thread's 5 oh, then reduce over 25 ow
    #pragma unroll
    for (int o = 0; o < 8; o++) {
        float b = b3[ocb*64 + og*8 + o];
        float m = -3.4e38f;
        #pragma unroll
        for (int h = 0; h < 5; h++) m = fmaxf(m, acc[o][h] + b);
        sred[(og*8 + o)*25 + ow] = m;
    }
    __syncthreads();
    if (tid < 64) {
        float m = -3.4e38f;
        #pragma unroll
        for (int w = 0; w < 25; w++) m = fmaxf(m, sred[tid*25 + w]);
        d_xf[(long)n*1024 + ocb*64 + tid] = m;
    }
}

// ---------------------------------------------------------------------------
// 8) L2-normalize xf -> feat[:, 8192:9216]
// ---------------------------------------------------------------------------
__global__ void xfnorm_kernel()
{
    __shared__ float sr[256];
    int n = blockIdx.x, tid = threadIdx.x;
    float v[4]; float s = 0.f;
    #pragma unroll
    for (int i = 0; i < 4; i++) {
        v[i] = d_xf[(long)n*1024 + tid + 256*i];
        s += v[i]*v[i];
    }
    sr[tid] = s; __syncthreads();
    for (int st = 128; st > 0; st >>= 1) {
        if (tid < st) sr[tid] += sr[tid + st];
        __syncthreads();
    }
    float nrm = fmaxf(sqrtf(sr[0]), 1e-12f);
    #pragma unroll
    for (int i = 0; i < 4; i++)
        d_feat[(long)n*9216 + 8192 + tid + 256*i] = v[i] / nrm;
}

// ---------------------------------------------------------------------------
// 9) MLP 9216->256 + final L2 norm.  grid 16, 256 thr (one per output j)
// ---------------------------------------------------------------------------
__global__ void __launch_bounds__(256) mlp_kernel(
    const float* __restrict__ mw, const float* __restrict__ mb,
    float* __restrict__ out)
{
    __shared__ float sf[9216];
    __shared__ float sr[256];
    int n = blockIdx.x, j = threadIdx.x;
    for (int i = j; i < 9216; i += 256) sf[i] = d_feat[(long)n*9216 + i];
    __syncthreads();
    float acc = mb[j];
    const float4* wr  = (const float4*)(mw + (long)j*9216);
    const float4* sf4 = (const float4*)sf;
    for (int i = 0; i < 2304; i++) {
        float4 w4 = wr[i], f4 = sf4[i];
        acc += w4.x*f4.x + w4.y*f4.y + w4.z*f4.z + w4.w*f4.w;
    }
    sr[j] = acc*acc; __syncthreads();
    for (int st = 128; st > 0; st >>= 1) {
        if (j < st) sr[j] += sr[j + st];
        __syncthreads();
    }
    float nrm = fmaxf(sqrtf(sr[0]), 1e-12f);
    out[n*256 + j] = acc / nrm;
}

// ---------------------------------------------------------------------------
extern "C" void kernel_launch(void* const* d_in, const int* in_sizes, int n_in,
                              void* d_out, int out_size)
{
    const float* x       = (const float*)d_in[0];
    const float* centers = (const float*)d_in[1];
    const float* cw      = (const float*)d_in[2];
    const float* cb      = (const float*)d_in[3];
    const float* w1      = (const float*)d_in[4];
    const float* b1      = (const float*)d_in[5];
    const float* w2      = (const float*)d_in[6];
    const float* b2      = (const float*)d_in[7];
    const float* w3      = (const float*)d_in[8];
    const float* b3      = (const float*)d_in[9];
    const float* mw      = (const float*)d_in[10];
    const float* mb      = (const float*)d_in[11];
    float* out = (float*)d_out;

    cudaFuncSetAttribute(assign_kernel,
        cudaFuncAttributeMaxDynamicSharedMemorySize, 155904);
    cudaFuncSetAttribute(conv5x5_kernel<128,40,200,256,true>,
        cudaFuncAttributeMaxDynamicSharedMemorySize, 57600);
    cudaFuncSetAttribute(conv5x5_kernel<256,20,100,512,false>,
        cudaFuncAttributeMaxDynamicSharedMemorySize, 57600);
    cudaFuncSetAttribute(conv3_kernel,
        cudaFuncAttributeMaxDynamicSharedMemorySize, 66208);

    // NetVLAD branch
    assign_kernel<<<dim3(50,16), 256, 155904>>>(x, cw, cb);
    asum_kernel<<<1024, 256>>>();
    vlad_kernel<<<dim3(8,16), 256>>>(x);
    vladreduce_kernel<<<1024, 128>>>(centers);
    vladglobal_kernel<<<16, 256>>>();

    // CNN branch
    conv5x5_kernel<128,40,200,256,true ><<<dim3(100,4,16), 160, 57600>>>(x, w1, b1);
    conv5x5_kernel<256,20,100,512,false><<<dim3(25, 8,16), 160, 57600>>>(nullptr, w2, b2);
    pool4_kernel<<<4000, 256>>>();
    conv3_kernel<<<dim3(16,16), 200, 66208>>>(w3, b3);
    xfnorm_kernel<<<16, 256>>>();

    // head
    mlp_kernel<<<16, 256>>>(mw, mb, out);
}